// round 17
// baseline (speedup 1.0000x reference)
#include <cuda_runtime.h>
#include <cuda_bf16.h>
#include <cstdint>

// Device-global scratch (no allocations). Zero-init; last block resets.
__device__ double        g_acc       = 0.0;
__device__ unsigned int  g_acc_count = 0;

#define LOG2E 1.44269504088896340736f
#define LN2   0.69314718055994530942f

__device__ __forceinline__ float rcp_approx(float x) {
    float r; asm("rcp.approx.f32 %0, %1;" : "=f"(r) : "f"(x)); return r;
}
__device__ __forceinline__ float ex2_approx(float x) {
    float r; asm("ex2.approx.f32 %0, %1;" : "=f"(r) : "f"(x)); return r;
}
__device__ __forceinline__ float lg2_approx(float x) {
    float r; asm("lg2.approx.f32 %0, %1;" : "=f"(r) : "f"(x)); return r;
}

// Streaming 128-bit loads with L2 256B prefetch hint (sequential stream).
__device__ __forceinline__ float4 ldg_f4_pf(const float4* p) {
    float4 v;
    asm("ld.global.nc.L2::256B.v4.f32 {%0,%1,%2,%3}, [%4];"
        : "=f"(v.x), "=f"(v.y), "=f"(v.z), "=f"(v.w) : "l"(p));
    return v;
}
__device__ __forceinline__ int4 ldg_i4_pf(const int4* p) {
    int4 v;
    asm("ld.global.nc.L2::256B.v4.u32 {%0,%1,%2,%3}, [%4];"
        : "=r"(v.x), "=r"(v.y), "=r"(v.z), "=r"(v.w) : "l"(p));
    return v;
}

// tbl[p*3+t] = { 1.5*P[p][t],  0.1*(p!=t),  class_w[t]*ln2,  0 }
__device__ __forceinline__ void row_loss(float l0, float l1, float l2, int t,
                                         const float4* __restrict__ tbl,
                                         float& acc, float& accP)
{
    // exact first-occurrence argmax (strict > matches jnp.argmax)
    const bool  pa  = (l1 > l0);
    const float m01 = fmaxf(l0, l1);
    const bool  pb  = (l2 > m01);
    const float m   = fmaxf(m01, l2);

    const int p3  = pb ? 6 : (pa ? 3 : 0);     // p * 3
    const float4 e = tbl[p3 + t];              // {pen15, confw, aln2, -}

    // log2-domain shifted deltas; max lane is exactly 0 -> exp = 1
    const float nmK = -m * LOG2E;
    const float s0 = fmaf(l0, LOG2E, nmK);
    const float s1 = fmaf(l1, LOG2E, nmK);
    const float s2 = fmaf(l2, LOG2E, nmK);

    const float e0 = ex2_approx(s0);
    const float e1 = ex2_approx(s1);
    const float e2 = ex2_approx(s2);
    const float S    = e0 + e1 + e2;
    const float rcpS = rcp_approx(S);          // == max prob (exp at argmax is 1)

    // pt = prob[target]; ce2 = -log2(pt)
    const float et = (t == 0) ? e0 : ((t == 1) ? e1 : e2);
    const float pt = et * rcpS;
    const float nq = lg2_approx(pt);           // log2(pt) <= 0
    const float omp = 1.0f - pt;

    const float w  = e.z * omp;                // alpha*ln2 * (1-pt)
    acc  = fmaf(w * omp, -nq, acc);            // focal (negation free in FMA)
    acc  = fmaf(e.y, rcpS, acc);               // 0.1*(p!=t)*max_prob
    accP += e.x;                               // 1.5*penalty
}

__global__ void __launch_bounds__(256, 6)
trading_loss_kernel(const float* __restrict__ logits,
                    const int*   __restrict__ targets,
                    const float* __restrict__ class_w,
                    float*       __restrict__ out,
                    int ngroups, float inv_n, int nblocks)
{
    __shared__ float4 tbl[9];
    __shared__ float  warp_sums[8];
    __shared__ bool   is_last;

    const int tid    = blockIdx.x * blockDim.x + threadIdx.x;
    const int stride = gridDim.x * blockDim.x;

    const float4* lbase = reinterpret_cast<const float4*>(logits);
    const int4*   tbase = reinterpret_cast<const int4*>(targets);

    // ---- issue the FIRST group's streaming loads before anything else ----
    // Their DRAM round-trip overlaps the class_w load, table build and barrier.
    const bool have0 = (tid < ngroups);
    float4 a0, a1, a2; int4 t4;
    if (have0) {
        a0 = ldg_f4_pf(lbase + (size_t)tid * 3 + 0);
        a1 = ldg_f4_pf(lbase + (size_t)tid * 3 + 1);
        a2 = ldg_f4_pf(lbase + (size_t)tid * 3 + 2);
        t4 = ldg_i4_pf(tbase + tid);
    }

    if (threadIdx.x < 9) {
        const int p = threadIdx.x / 3;
        const int t = threadIdx.x - p * 3;
        int d = p - t; d = (d < 0) ? -d : d;
        const float pen15 = 0.75f * (float)d + ((d == 2) ? 0.75f : 0.0f);
        const float confw = (d != 0) ? 0.1f : 0.0f;
        tbl[threadIdx.x] = make_float4(pen15, confw, class_w[t] * LN2, 0.0f);
    }
    __syncthreads();

    float acc0 = 0.0f, acc1 = 0.0f, accP = 0.0f;

    // peeled first iteration
    if (have0) {
        row_loss(a0.x, a0.y, a0.z, t4.x, tbl, acc0, accP);
        row_loss(a0.w, a1.x, a1.y, t4.y, tbl, acc1, accP);
        row_loss(a1.z, a1.w, a2.x, t4.z, tbl, acc0, accP);
        row_loss(a2.y, a2.z, a2.w, t4.w, tbl, acc1, accP);
    }

    // steady state — identical body to the champion kernel
    for (int g = tid + stride; g < ngroups; g += stride) {
        const float4 b0 = ldg_f4_pf(lbase + (size_t)g * 3 + 0);
        const float4 b1 = ldg_f4_pf(lbase + (size_t)g * 3 + 1);
        const float4 b2 = ldg_f4_pf(lbase + (size_t)g * 3 + 2);
        const int4   u4 = ldg_i4_pf(tbase + g);

        row_loss(b0.x, b0.y, b0.z, u4.x, tbl, acc0, accP);
        row_loss(b0.w, b1.x, b1.y, u4.y, tbl, acc1, accP);
        row_loss(b1.z, b1.w, b2.x, u4.z, tbl, acc0, accP);
        row_loss(b2.y, b2.z, b2.w, u4.w, tbl, acc1, accP);
    }

    float acc = (acc0 + acc1) + accP;

    // ---- block reduction ----
    #pragma unroll
    for (int off = 16; off > 0; off >>= 1)
        acc += __shfl_xor_sync(0xFFFFFFFFu, acc, off);

    const int lane = threadIdx.x & 31;
    const int wid  = threadIdx.x >> 5;
    if (lane == 0) warp_sums[wid] = acc;
    __syncthreads();

    if (wid == 0) {
        float v = (lane < (blockDim.x >> 5)) ? warp_sums[lane] : 0.0f;
        #pragma unroll
        for (int off = 4; off > 0; off >>= 1)
            v += __shfl_xor_sync(0xFFFFFFFFu, v, off);
        if (lane == 0) {
            atomicAdd(&g_acc, (double)v);
            __threadfence();
            unsigned int ticket = atomicAdd(&g_acc_count, 1u);
            is_last = (ticket == (unsigned int)nblocks - 1u);
        }
    }
    __syncthreads();

    if (is_last && threadIdx.x == 0) {
        double total = g_acc;
        out[0] = (float)(total * (double)inv_n);
        g_acc = 0.0;
        g_acc_count = 0u;
    }
}

extern "C" void kernel_launch(void* const* d_in, const int* in_sizes, int n_in,
                              void* d_out, int out_size)
{
    const float* logits  = (const float*)d_in[0];
    const int*   targets = (const int*)d_in[1];
    const float* class_w = (const float*)d_in[2];
    float*       out     = (float*)d_out;

    const int batch   = in_sizes[1];       // targets element count = B
    const int ngroups = batch / 4;         // 4 rows per float4-group

    const int threads = 256;
    int blocks = 152 * 6;                  // single resident wave (GB300: 152 SMs)
    int maxb   = (ngroups + threads - 1) / threads;
    if (blocks > maxb) blocks = maxb;
    if (blocks < 1) blocks = 1;

    trading_loss_kernel<<<blocks, threads>>>(logits, targets, class_w, out,
                                             ngroups, 1.0f / (float)batch, blocks);
}